// round 6
// baseline (speedup 1.0000x reference)
#include <cuda_runtime.h>
#include <cstdint>

#define NN 8192
#define HH 256
#define TOPK 16
#define NSEC 11
#define NEG_SLOPE 0.2f
#define CCH 4            // column chunks (64 cols each)
#define CW  64           // cols per chunk
#define RT  128          // rows per tile

// ---------------- device scratch (no allocations allowed) ----------------
__device__ __align__(16) float g_p1[CCH][NN];   // partial s1 per column chunk
__device__ __align__(16) float g_p2[CCH][NN];   // partial s2 per column chunk

// ---------------- helpers ----------------
__device__ __forceinline__ bool is_active(const void* am, int i, int mode) {
    if (mode == 0) return ((const unsigned char*)am)[i] != 0;
    if (mode == 1) return ((const int*)am)[i] != 0;
    return ((const float*)am)[i] != 0.0f;
}

__device__ __forceinline__ unsigned long long umax64(unsigned long long a,
                                                     unsigned long long b) {
    return a > b ? a : b;
}

// ============================================================================
// Kernel 1 (CCH*64 = 256 blocks, 256 threads): fused projection + scores.
// Block (chunk, tile) computes v1/v2 for its 64-column chunk from W (L2-
// shared across the 64 tiles of the chunk), then partial dot products of its
// 128 E-rows against that chunk:  g_p{1,2}[chunk][row] = E[row,chunk]·v{1,2}.
// No cross-block ordering, no atomics -> deterministic, single launch.
// ============================================================================
__global__ void __launch_bounds__(256)
k_scores(const float* __restrict__ E, const float* __restrict__ W,
         const float* __restrict__ a) {
    int chunk = blockIdx.x & (CCH - 1);
    int tile  = blockIdx.x >> 2;
    int t     = threadIdx.x;           // 256
    int c0f4  = chunk * (CW / 4);      // chunk col offset in float4 units (16)

    __shared__ float  sa1[HH], sa2[HH];
    __shared__ float4 red1[16][16], red2[16][16];
    __shared__ float4 sv1[16], sv2[16];

    sa1[t] = a[t];
    sa2[t] = a[HH + t];
    __syncthreads();

    // ---- proj for this chunk: v[c] = sum_k W[k,c]*a[k], c in chunk ----
    {
        int cg = t & 15;               // float4 col group within chunk
        int ks = t >> 4;               // 16 k-subsets of 16 rows each
        const float4* W4 = (const float4*)W;
        float4 a1v = make_float4(0.f, 0.f, 0.f, 0.f);
        float4 a2v = make_float4(0.f, 0.f, 0.f, 0.f);
#pragma unroll
        for (int kk = 0; kk < 16; kk++) {
            int k = ks * 16 + kk;
            float4 w = W4[k * 64 + c0f4 + cg];
            float x1 = sa1[k], x2 = sa2[k];
            a1v.x = fmaf(w.x, x1, a1v.x); a1v.y = fmaf(w.y, x1, a1v.y);
            a1v.z = fmaf(w.z, x1, a1v.z); a1v.w = fmaf(w.w, x1, a1v.w);
            a2v.x = fmaf(w.x, x2, a2v.x); a2v.y = fmaf(w.y, x2, a2v.y);
            a2v.z = fmaf(w.z, x2, a2v.z); a2v.w = fmaf(w.w, x2, a2v.w);
        }
        red1[ks][cg] = a1v;
        red2[ks][cg] = a2v;
    }
    __syncthreads();
    if (t < 32) {
        int which = t >> 4, cg = t & 15;
        float4 s = make_float4(0.f, 0.f, 0.f, 0.f);
#pragma unroll
        for (int ks = 0; ks < 16; ks++) {
            float4 x = which ? red2[ks][cg] : red1[ks][cg];
            s.x += x.x; s.y += x.y; s.z += x.z; s.w += x.w;
        }
        if (which) sv2[cg] = s; else sv1[cg] = s;
    }
    __syncthreads();

    // ---- partial scores: 8 warps x 16 rows, half-warp per row ----
    int wp = t >> 5, lane = t & 31;
    int half = lane >> 4, hl = lane & 15;
    const float4* E4 = (const float4*)E;
    float4 v = sv1[hl];
    float4 u = sv2[hl];
#pragma unroll
    for (int r = 0; r < 8; r++) {
        int row = tile * RT + wp * 16 + r * 2 + half;
        float4 x = E4[(size_t)row * 64 + c0f4 + hl];
        float d1 = fmaf(x.x, v.x, fmaf(x.y, v.y, fmaf(x.z, v.z, x.w * v.w)));
        float d2 = fmaf(x.x, u.x, fmaf(x.y, u.y, fmaf(x.z, u.z, x.w * u.w)));
#pragma unroll
        for (int o = 8; o; o >>= 1) {
            d1 += __shfl_xor_sync(0xFFFFFFFFu, d1, o);
            d2 += __shfl_xor_sync(0xFFFFFFFFu, d2, o);
        }
        if (hl == 0) {
            g_p1[chunk][row] = d1;
            g_p2[chunk][row] = d2;
        }
    }
}

// ============================================================================
// Kernel 2: per-sector top-16 (warp tournament) + output emission, with a
// block-local mask-dtype detect. One 1024-thread block per sector.
// Key = (monotone_u32(s2) << 32) | ~j  -> max-order == (s2 desc, idx asc),
// matching jax.lax.top_k tie-breaking. Key 0 is an impossible sentinel.
// ============================================================================
__global__ void __launch_bounds__(1024, 1)
k_topk_out(const int* __restrict__ sector, const void* __restrict__ am,
           float* __restrict__ out, int out_size) {
    int sec  = blockIdx.x;
    int tid  = threadIdx.x;            // 1024
    int lane = tid & 31, wp = tid >> 5;

    // ---- local detect of active_mask storage dtype (scan NN bytes) ----
    __shared__ unsigned s_g[32], s_o[32], s_a[32];
    __shared__ int s_mode;
    {
        unsigned gt1 = 0, nzo = 0, nza = 0;
        if (tid < NN / 16) {           // 512 uint4 cover 8192 bytes
            uint4 v = ((const uint4*)am)[tid];
            unsigned ws[4] = {v.x, v.y, v.z, v.w};
#pragma unroll
            for (int j = 0; j < 4; j++) {
                unsigned w = ws[j];
                gt1 |= (w & 0xFEFEFEFEu);   // any byte with bits 1..7 set
                nza |= (w & 0x000000FFu);   // byte at p%4==0
                nzo |= (w & 0xFFFFFF00u);   // bytes at p%4!=0
            }
        }
        unsigned bg = __ballot_sync(0xFFFFFFFFu, gt1 != 0);
        unsigned bo = __ballot_sync(0xFFFFFFFFu, nzo != 0);
        unsigned ba = __ballot_sync(0xFFFFFFFFu, nza != 0);
        if (lane == 0) { s_g[wp] = bg; s_o[wp] = bo; s_a[wp] = ba; }
        __syncthreads();
        if (tid == 0) {
            unsigned G = 0, O = 0, A = 0;
#pragma unroll
            for (int j = 0; j < 32; j++) { G |= s_g[j]; O |= s_o[j]; A |= s_a[j]; }
            int mode;
            if (G) mode = A ? 0 : 2;   // f32 truth bytes live at p%4==2,3
            else   mode = O ? 0 : 1;
            s_mode = mode;
        }
        __syncthreads();
    }
    int mode = s_mode;

    // ---- gather candidates (sum chunk partials; fixed order) ----
    unsigned long long cand[8];
#pragma unroll
    for (int t = 0; t < 8; t++) {
        int i = tid + (t << 10);
        unsigned long long key = 0ull;
        if (sector[i] == sec && is_active(am, i, mode)) {
            float s2 = ((g_p2[0][i] + g_p2[1][i]) + (g_p2[2][i] + g_p2[3][i]));
            unsigned u = __float_as_uint(s2);
            u = (u & 0x80000000u) ? ~u : (u | 0x80000000u);
            key = ((unsigned long long)u << 32) | (unsigned)(~i);
        }
        cand[t] = key;
    }

    // ---- level 1: each warp pops its top-16 via shfl-max rounds ----
    __shared__ unsigned long long warp_top[32][16];
#pragma unroll 1
    for (int r = 0; r < 16; r++) {
        unsigned long long m = cand[0];
#pragma unroll
        for (int j = 1; j < 8; j++) m = umax64(m, cand[j]);
        unsigned long long w = m;
#pragma unroll
        for (int o = 16; o; o >>= 1)
            w = umax64(w, __shfl_xor_sync(0xFFFFFFFFu, w, o));
        if (w != 0ull && m == w) {     // unique winner clears its element
            bool done = false;
#pragma unroll
            for (int j = 0; j < 8; j++)
                if (!done && cand[j] == w) { cand[j] = 0ull; done = true; }
        }
        if (lane == 0) warp_top[wp][r] = w;   // sorted desc per warp
    }
    __syncthreads();

    // ---- level 2: warp 0 merges the 32 sorted 16-lists ----
    __shared__ int   s_idx[TOPK];
    __shared__ float s_w2[TOPK];
    __shared__ int   s_cnt;
    if (wp == 0) {
        int h = 0, cnt = 0;
#pragma unroll 1
        for (int r = 0; r < 16; r++) {
            unsigned long long v = (h < 16) ? warp_top[lane][h] : 0ull;
            unsigned long long w = v;
#pragma unroll
            for (int o = 16; o; o >>= 1)
                w = umax64(w, __shfl_xor_sync(0xFFFFFFFFu, w, o));
            if (w != 0ull && v == w) h++;
            if (lane == 0 && w != 0ull) {
                unsigned hi = (unsigned)(w >> 32);
                s_idx[r] = (int)(~(unsigned)(w & 0xFFFFFFFFull));
                // invert the monotone transform to recover s2
                s_w2[r]  = __uint_as_float(
                    (hi & 0x80000000u) ? (hi & 0x7FFFFFFFu) : ~hi);
                cnt = r + 1;
            }
        }
        if (lane == 0) {
            // fill remaining slots with smallest NON-member indices (the -inf
            // ties; jax top_k picks them in ascending index order)
            int k = cnt, j = 0;
            while (k < TOPK && j < NN) {
                bool mem = (sector[j] == sec) && is_active(am, j, mode);
                if (!mem) { s_idx[k] = j; s_w2[k] = 0.f; k++; }
                j++;
            }
            while (k < TOPK) { s_idx[k] = 0; s_w2[k] = 0.f; k++; }
            s_cnt = cnt;
        }
    }
    __syncthreads();

    // ---- output: each thread emits the 16-tuples for its sector rows ----
    int cnt = s_cnt;
    const int NT = NN * TOPK;
    bool w_idx = (out_size >= 2 * NT);
    bool w_val = (out_size >= 3 * NT);
#pragma unroll 1
    for (int t = 0; t < 8; t++) {
        int i = tid + (t << 10);
        if (sector[i] != sec) continue;
        bool act = is_active(am, i, mode);
        float s1 = 0.f;
        if (act) s1 = ((g_p1[0][i] + g_p1[1][i]) + (g_p1[2][i] + g_p1[3][i]));
#pragma unroll
        for (int k = 0; k < TOPK; k += 4) {
            float wv[4], iv[4], vv[4];
#pragma unroll
            for (int q = 0; q < 4; q++) {
                int kk = k + q;
                if (!act) {
                    // whole row is -inf: top_k returns indices 0..15, invalid
                    wv[q] = 0.f; iv[q] = (float)kk; vv[q] = 0.f;
                } else if (kk < cnt) {
                    float x = s1 + s_w2[kk];
                    wv[q] = (x >= 0.f) ? x : NEG_SLOPE * x;  // leaky_relu, T=1
                    iv[q] = (float)s_idx[kk]; vv[q] = 1.f;
                } else {
                    wv[q] = 0.f; iv[q] = (float)s_idx[kk]; vv[q] = 0.f;
                }
            }
            int o = i * TOPK + k;
            *(float4*)&out[o] = make_float4(wv[0], wv[1], wv[2], wv[3]);
            if (w_idx) *(float4*)&out[NT + o]     = make_float4(iv[0], iv[1], iv[2], iv[3]);
            if (w_val) *(float4*)&out[2 * NT + o] = make_float4(vv[0], vv[1], vv[2], vv[3]);
        }
    }
}

extern "C" void kernel_launch(void* const* d_in, const int* in_sizes, int n_in,
                              void* d_out, int out_size) {
    const float* E      = (const float*)d_in[0];   // embeddings [N, H]
    const float* W      = (const float*)d_in[1];   // W [H, H]
    const float* a      = (const float*)d_in[2];   // a [2H]
    const int*   sector = (const int*)d_in[3];     // sector_ids [N]
    const void*  am     = d_in[4];                 // active_mask [N]
    float* out = (float*)d_out;

    k_scores  <<<CCH * (NN / RT), 256>>>(E, W, a);
    k_topk_out<<<NSEC, 1024>>>(sector, am, out, out_size);
}

// round 9
// speedup vs baseline: 1.4491x; 1.4491x over previous
#include <cuda_runtime.h>
#include <cstdint>

#define NN 8192
#define HH 256
#define TOPK 16
#define NSEC 11
#define NEG_SLOPE 0.2f
#define CCH 4            // column chunks (64 cols each)
#define CW  64
#define RT  128          // rows per score tile
#define CAP 2048         // compacted-member capacity per sector (E[m]~372)

// ---------------- device scratch (no allocations allowed) ----------------
__device__ __align__(16) float g_p1[CCH][NN];   // partial s1 per column chunk
__device__ __align__(16) float g_p2[CCH][NN];   // partial s2 per column chunk
__device__ int   g_mask_mode;                   // 0=u8, 1=i32, 2=f32
__device__ int   g_tidx[NSEC][TOPK];
__device__ float g_ts2[NSEC][TOPK];
__device__ int   g_tcnt[NSEC];

// ---------------- helpers ----------------
__device__ __forceinline__ bool is_active(const void* am, int i, int mode) {
    if (mode == 0) return ((const unsigned char*)am)[i] != 0;
    if (mode == 1) return ((const int*)am)[i] != 0;
    return ((const float*)am)[i] != 0.0f;
}

__device__ __forceinline__ unsigned long long umax64(unsigned long long a,
                                                     unsigned long long b) {
    return a > b ? a : b;
}

// ============================================================================
// Kernel 1 (CCH*64 + 1 blocks, 256 threads): fused projection + scores.
// Block (chunk, tile) computes v1/v2 for its 64-column chunk from W, then
// partial dot products of its 128 E-rows: g_p{1,2}[chunk][row].
// The extra last block detects the active_mask storage dtype (hidden under
// the 256 score blocks).
// ============================================================================
__global__ void __launch_bounds__(256)
k_scores(const float* __restrict__ E, const float* __restrict__ W,
         const float* __restrict__ a, const unsigned char* __restrict__ am) {
    int t = threadIdx.x;
    if (blockIdx.x == CCH * (NN / RT)) {
        // ---- detect active_mask dtype: scan first NN bytes as uint4 ----
        const uint4* am4 = (const uint4*)am;
        unsigned gt1 = 0, nzo = 0, nza = 0;
#pragma unroll
        for (int it = 0; it < NN / (256 * 16); it++) {   // 2 iterations
            uint4 v = am4[t + it * 256];
            unsigned ws[4] = {v.x, v.y, v.z, v.w};
#pragma unroll
            for (int j = 0; j < 4; j++) {
                unsigned w = ws[j];
                gt1 |= (w & 0xFEFEFEFEu);   // any byte with bits 1..7 set
                nza |= (w & 0x000000FFu);   // byte at p%4==0
                nzo |= (w & 0xFFFFFF00u);   // bytes at p%4!=0
            }
        }
        __shared__ unsigned s_g[8], s_o[8], s_a[8];
        unsigned bg = __ballot_sync(0xFFFFFFFFu, gt1 != 0);
        unsigned bo = __ballot_sync(0xFFFFFFFFu, nzo != 0);
        unsigned ba = __ballot_sync(0xFFFFFFFFu, nza != 0);
        if ((t & 31) == 0) { s_g[t >> 5] = bg; s_o[t >> 5] = bo; s_a[t >> 5] = ba; }
        __syncthreads();
        if (t == 0) {
            unsigned G = 0, O = 0, A = 0;
#pragma unroll
            for (int j = 0; j < 8; j++) { G |= s_g[j]; O |= s_o[j]; A |= s_a[j]; }
            int mode;
            if (G) mode = A ? 0 : 2;    // f32 truth bytes live at p%4==2,3
            else   mode = O ? 0 : 1;
            g_mask_mode = mode;
        }
        return;
    }

    int chunk = blockIdx.x & (CCH - 1);
    int tile  = blockIdx.x >> 2;
    int c0f4  = chunk * (CW / 4);      // chunk col offset in float4 units

    __shared__ float  sa1[HH], sa2[HH];
    __shared__ float4 red1[16][16], red2[16][16];
    __shared__ float4 sv1[16], sv2[16];

    sa1[t] = a[t];
    sa2[t] = a[HH + t];
    __syncthreads();

    // ---- proj for this chunk: v[c] = sum_k W[k,c]*a[k] ----
    {
        int cg = t & 15;               // float4 col group within chunk
        int ks = t >> 4;               // 16 k-subsets of 16 rows each
        const float4* W4 = (const float4*)W;
        float4 a1v = make_float4(0.f, 0.f, 0.f, 0.f);
        float4 a2v = make_float4(0.f, 0.f, 0.f, 0.f);
#pragma unroll
        for (int kk = 0; kk < 16; kk++) {
            int k = ks * 16 + kk;
            float4 w = W4[k * 64 + c0f4 + cg];
            float x1 = sa1[k], x2 = sa2[k];
            a1v.x = fmaf(w.x, x1, a1v.x); a1v.y = fmaf(w.y, x1, a1v.y);
            a1v.z = fmaf(w.z, x1, a1v.z); a1v.w = fmaf(w.w, x1, a1v.w);
            a2v.x = fmaf(w.x, x2, a2v.x); a2v.y = fmaf(w.y, x2, a2v.y);
            a2v.z = fmaf(w.z, x2, a2v.z); a2v.w = fmaf(w.w, x2, a2v.w);
        }
        red1[ks][cg] = a1v;
        red2[ks][cg] = a2v;
    }
    __syncthreads();
    if (t < 32) {
        int which = t >> 4, cg = t & 15;
        float4 s = make_float4(0.f, 0.f, 0.f, 0.f);
#pragma unroll
        for (int ks = 0; ks < 16; ks++) {
            float4 x = which ? red2[ks][cg] : red1[ks][cg];
            s.x += x.x; s.y += x.y; s.z += x.z; s.w += x.w;
        }
        if (which) sv2[cg] = s; else sv1[cg] = s;
    }
    __syncthreads();

    // ---- partial scores: 8 warps x 16 rows, half-warp per row ----
    int wp = t >> 5, lane = t & 31;
    int half = lane >> 4, hl = lane & 15;
    const float4* E4 = (const float4*)E;
    float4 v = sv1[hl];
    float4 u = sv2[hl];
#pragma unroll
    for (int r = 0; r < 8; r++) {
        int row = tile * RT + wp * 16 + r * 2 + half;
        float4 x = E4[(size_t)row * 64 + c0f4 + hl];
        float d1 = fmaf(x.x, v.x, fmaf(x.y, v.y, fmaf(x.z, v.z, x.w * v.w)));
        float d2 = fmaf(x.x, u.x, fmaf(x.y, u.y, fmaf(x.z, u.z, x.w * u.w)));
#pragma unroll
        for (int o = 8; o; o >>= 1) {
            d1 += __shfl_xor_sync(0xFFFFFFFFu, d1, o);
            d2 += __shfl_xor_sync(0xFFFFFFFFu, d2, o);
        }
        if (hl == 0) {
            g_p1[chunk][row] = d1;
            g_p2[chunk][row] = d2;
        }
    }
}

// ============================================================================
// Kernel 2 (NSEC blocks, 1024 threads): compact sector members into smem via
// warp-aggregated atomics, then single-warp tournament over the compacted
// list. Result set is order-independent (max over unique keys) ->
// deterministic. Key = (monotone_u32(s2)<<32) | ~j.
// ============================================================================
__global__ void __launch_bounds__(1024, 1)
k_topk(const int* __restrict__ sector, const void* __restrict__ am) {
    int sec  = blockIdx.x;
    int tid  = threadIdx.x;
    int lane = tid & 31, wp = tid >> 5;
    int mode = g_mask_mode;

    __shared__ unsigned long long keys[CAP];
    __shared__ int s_n;
    if (tid == 0) s_n = 0;
    __syncthreads();

#pragma unroll
    for (int t = 0; t < 8; t++) {
        int i = tid + (t << 10);
        bool mem = (sector[i] == sec) && is_active(am, i, mode);
        unsigned long long key = 0ull;
        if (mem) {
            float s2 = (g_p2[0][i] + g_p2[1][i]) + (g_p2[2][i] + g_p2[3][i]);
            unsigned u = __float_as_uint(s2);
            u = (u & 0x80000000u) ? ~u : (u | 0x80000000u);
            key = ((unsigned long long)u << 32) | (unsigned)(~i);
        }
        unsigned bal = __ballot_sync(0xFFFFFFFFu, mem);
        int nb  = __popc(bal);
        int ldr = nb ? (__ffs(bal) - 1) : 0;
        int base = 0;
        if (nb && lane == ldr) base = atomicAdd(&s_n, nb);
        base = __shfl_sync(0xFFFFFFFFu, base, ldr);
        if (mem) {
            int pos = base + __popc(bal & ((1u << lane) - 1u));
            if (pos < CAP) keys[pos] = key;
        }
    }
    __syncthreads();

    if (wp == 0) {
        int M = s_n < CAP ? s_n : CAP;
        int cnt = 0;
#pragma unroll 1
        for (int r = 0; r < TOPK; r++) {
            unsigned long long m = 0ull;
            int mi = -1;
            for (int j = lane; j < M; j += 32) {
                unsigned long long v = keys[j];
                if (v > m) { m = v; mi = j; }
            }
            unsigned long long w = m;
#pragma unroll
            for (int o = 16; o; o >>= 1)
                w = umax64(w, __shfl_xor_sync(0xFFFFFFFFu, w, o));
            if (w == 0ull) break;
            if (m == w && mi >= 0) keys[mi] = 0ull;  // unique key -> one lane
            if (lane == 0) {
                unsigned hi = (unsigned)(w >> 32);
                g_tidx[sec][r] = (int)(~(unsigned)(w & 0xFFFFFFFFull));
                g_ts2[sec][r]  = __uint_as_float(
                    (hi & 0x80000000u) ? (hi & 0x7FFFFFFFu) : ~hi);
            }
            cnt = r + 1;
        }
        if (lane == 0) {
            // fill remaining slots with smallest NON-member indices (-inf
            // ties; jax top_k picks them in ascending index order)
            int k = cnt, j = 0;
            while (k < TOPK && j < NN) {
                bool mem = (sector[j] == sec) && is_active(am, j, mode);
                if (!mem) { g_tidx[sec][k] = j; g_ts2[sec][k] = 0.f; k++; }
                j++;
            }
            while (k < TOPK) { g_tidx[sec][k] = 0; g_ts2[sec][k] = 0.f; k++; }
            g_tcnt[sec] = cnt;
        }
    }
}

// ============================================================================
// Kernel 3 (64 blocks, 128 threads): one thread per row; emit all outputs.
// ============================================================================
__global__ void __launch_bounds__(128)
k_emit(const int* __restrict__ sector, const void* __restrict__ am,
       float* __restrict__ out, int out_size) {
    __shared__ int   s_idx[NSEC][TOPK];
    __shared__ float s_s2[NSEC][TOPK];
    __shared__ int   s_cnt[NSEC];
    int tid = threadIdx.x;
    for (int q = tid; q < NSEC * TOPK; q += 128) {
        int s = q >> 4, k = q & 15;
        s_idx[s][k] = g_tidx[s][k];
        s_s2[s][k]  = g_ts2[s][k];
        if (k == 0) s_cnt[s] = g_tcnt[s];
    }
    __syncthreads();

    int mode = g_mask_mode;
    int row  = blockIdx.x * 128 + tid;
    bool act = is_active(am, row, mode);
    int  sc  = sector[row];
    float s1 = 0.f;
    if (act) s1 = (g_p1[0][row] + g_p1[1][row]) + (g_p1[2][row] + g_p1[3][row]);
    int cnt = s_cnt[sc];

    const int NT = NN * TOPK;
    bool w_idx = (out_size >= 2 * NT);
    bool w_val = (out_size >= 3 * NT);
#pragma unroll
    for (int k = 0; k < TOPK; k += 4) {
        float wv[4], iv[4], vv[4];
#pragma unroll
        for (int q = 0; q < 4; q++) {
            int kk = k + q;
            if (!act) {
                // whole row is -inf: top_k returns indices 0..15, invalid
                wv[q] = 0.f; iv[q] = (float)kk; vv[q] = 0.f;
            } else if (kk < cnt) {
                float x = s1 + s_s2[sc][kk];
                wv[q] = (x >= 0.f) ? x : NEG_SLOPE * x;  // leaky_relu, T=1
                iv[q] = (float)s_idx[sc][kk]; vv[q] = 1.f;
            } else {
                wv[q] = 0.f; iv[q] = (float)s_idx[sc][kk]; vv[q] = 0.f;
            }
        }
        int o = row * TOPK + k;
        *(float4*)&out[o] = make_float4(wv[0], wv[1], wv[2], wv[3]);
        if (w_idx) *(float4*)&out[NT + o]     = make_float4(iv[0], iv[1], iv[2], iv[3]);
        if (w_val) *(float4*)&out[2 * NT + o] = make_float4(vv[0], vv[1], vv[2], vv[3]);
    }
}

extern "C" void kernel_launch(void* const* d_in, const int* in_sizes, int n_in,
                              void* d_out, int out_size) {
    const float* E      = (const float*)d_in[0];   // embeddings [N, H]
    const float* W      = (const float*)d_in[1];   // W [H, H]
    const float* a      = (const float*)d_in[2];   // a [2H]
    const int*   sector = (const int*)d_in[3];     // sector_ids [N]
    const void*  am     = d_in[4];                 // active_mask [N]
    float* out = (float*)d_out;

    k_scores<<<CCH * (NN / RT) + 1, 256>>>(E, W, a, (const unsigned char*)am);
    k_topk  <<<NSEC, 1024>>>(sector, am);
    k_emit  <<<NN / 128, 128>>>(sector, am, out, out_size);
}